// round 9
// baseline (speedup 1.0000x reference)
#include <cuda_runtime.h>
#include <cuda_fp16.h>
#include <cstdint>

#define DIN     4096
#define RANK    64
#define MTOT    8192
#define NR      512
#define HCOLS   1536
#define DOUT    4096
#define OUTCOLS 12288

// fp16 staging buffers (device globals; no runtime allocation allowed)
__device__ __align__(16) __half g_Xh[(size_t)MTOT * DIN];    // 64 MB
__device__ __align__(16) __half g_Ah[(size_t)HCOLS * DIN];   // 12.5 MB  [j][k]
__device__ __align__(16) __half g_Bh[(size_t)3 * DOUT * NR]; // 12.5 MB  [comp][n][k]
__device__ __align__(16) __half g_Hh[(size_t)MTOT * HCOLS];  // 25 MB    [m][j]
__device__ int g_rowcnt[MTOT / 128];                         // H row-block readiness (0..12)

// ---------------------------------------------------------------------------
// PTX helpers
// ---------------------------------------------------------------------------
__device__ __forceinline__ uint32_t s2u(const void* p) {
    uint32_t a;
    asm("{ .reg .u64 t; cvta.to.shared.u64 t, %1; cvt.u32.u64 %0, t; }" : "=r"(a) : "l"(p));
    return a;
}
__device__ __forceinline__ void cpasync16(uint32_t dst, const void* src) {
    asm volatile("cp.async.cg.shared.global [%0], [%1], 16;" :: "r"(dst), "l"(src) : "memory");
}
#define CP_COMMIT()  asm volatile("cp.async.commit_group;" ::: "memory")
#define CP_WAIT(n)   asm volatile("cp.async.wait_group %0;" :: "n"(n) : "memory")

__device__ __forceinline__ void ldsm4(uint32_t* r, uint32_t a) {
    asm volatile("ldmatrix.sync.aligned.m8n8.x4.shared.b16 {%0,%1,%2,%3}, [%4];"
                 : "=r"(r[0]), "=r"(r[1]), "=r"(r[2]), "=r"(r[3]) : "r"(a));
}
__device__ __forceinline__ void mma16816(float* c, const uint32_t* a, const uint32_t* b) {
    asm volatile(
        "mma.sync.aligned.m16n8k16.row.col.f32.f16.f16.f32 "
        "{%0,%1,%2,%3},{%4,%5,%6,%7},{%8,%9},{%0,%1,%2,%3};"
        : "+f"(c[0]), "+f"(c[1]), "+f"(c[2]), "+f"(c[3])
        : "r"(a[0]), "r"(a[1]), "r"(a[2]), "r"(a[3]), "r"(b[0]), "r"(b[1]));
}
// smem tile row = 64 halves = 128B = 8 chunks of 16B; swizzle chunk ^= row&7
__device__ __forceinline__ uint32_t swz(int row, int chunk) {
    return (uint32_t)(row * 8 + (chunk ^ (row & 7))) * 16u;
}

// ---------------------------------------------------------------------------
// Prep kernels
// ---------------------------------------------------------------------------
__global__ void init_flags_k() {
    if (threadIdx.x < MTOT / 128) g_rowcnt[threadIdx.x] = 0;
}

__global__ void convx_k(const float* __restrict__ x) {
    size_t i = ((size_t)blockIdx.x * 512 + threadIdx.x) * 8;
    float4 a = *(const float4*)(x + i);
    float4 b = *(const float4*)(x + i + 4);
    __half2 h[4];
    h[0] = __floats2half2_rn(a.x, a.y);
    h[1] = __floats2half2_rn(a.z, a.w);
    h[2] = __floats2half2_rn(b.x, b.y);
    h[3] = __floats2half2_rn(b.z, b.w);
    *(uint4*)(g_Xh + i) = *(uint4*)h;
}

__global__ void transA_k(const float* __restrict__ qA, const float* __restrict__ kA,
                         const float* __restrict__ vA) {
    __shared__ float t[32][33];
    int z = blockIdx.z, comp = z >> 3, n = z & 7;
    const float* src = (comp == 0 ? qA : (comp == 1 ? kA : vA)) + (size_t)n * DIN * RANK;
    int i0 = blockIdx.x * 32, r0 = blockIdx.y * 32;
    int tx = threadIdx.x, ty = threadIdx.y;
    #pragma unroll
    for (int q = 0; q < 4; q++)
        t[ty + q * 8][tx] = src[(size_t)(i0 + ty + q * 8) * RANK + r0 + tx];
    __syncthreads();
    size_t jb = (size_t)(comp * 512 + n * 64 + r0);
    #pragma unroll
    for (int q = 0; q < 4; q++)
        g_Ah[(jb + ty + q * 8) * DIN + i0 + tx] = __float2half_rn(t[tx][ty + q * 8]);
}

__global__ void transB_k(const float* __restrict__ qB, const float* __restrict__ kB,
                         const float* __restrict__ vB) {
    __shared__ float t[32][33];
    int comp = blockIdx.z;
    const float* src = (comp == 0 ? qB : (comp == 1 ? kB : vB));  // [512][4096]
    int k0 = blockIdx.x * 32, n0 = blockIdx.y * 32;
    int tx = threadIdx.x, ty = threadIdx.y;
    #pragma unroll
    for (int q = 0; q < 4; q++)
        t[ty + q * 8][tx] = src[(size_t)(k0 + ty + q * 8) * DOUT + n0 + tx];
    __syncthreads();
    __half* dst = g_Bh + (size_t)comp * DOUT * NR;
    #pragma unroll
    for (int q = 0; q < 4; q++)
        dst[(size_t)(n0 + ty + q * 8) * NR + k0 + tx] = __float2half_rn(t[tx][ty + q * 8]);
}

// ---------------------------------------------------------------------------
// Streaming GEMM core with cross-barrier fragment pipelining.
// Tile = 128x128, warp tile m64 x n64, BK=64, 3-stage cp.async.
// CP_WAIT(1) guarantees stages s AND s+1 resident -> ks=3 prefetches the NEXT
// ktile's ks=0 fragments (same or next tile) under the current MMAs, so the
// LDSM->HMMA chain never drains. Second barrier protects slot reuse.
// ---------------------------------------------------------------------------
constexpr int STAGE_B = 32 * 1024;   // 16KB A + 16KB B
constexpr int BSTAGES = 3;

struct TilePtrs { const __half* Ag; const __half* Bg; int lda; int ldb; };

template <int NT, int LOGNT, class TF, class GF, class EF>
__device__ __forceinline__ void stream_gemm(int ntiles, TF tilef, GF guardf, EF epif,
                                            char* sm) {
    const int tid  = threadIdx.x;
    const int lane = tid & 31;
    const int wid  = tid >> 5;
    const int wm   = wid & 1;
    const int wn   = wid >> 1;
    uint32_t smu = s2u(sm);
    const int S = ntiles << LOGNT;
    if (S <= 0) return;

    auto issue = [&](int s) {
        const int it = s >> LOGNT;
        const int kt = s & (NT - 1);
        TilePtrs tp = tilef(it);
        const int slot = s % BSTAGES;
        const uint32_t sa = smu + slot * STAGE_B;
        const uint32_t sb = sa + 16384;
        const char* agb = (const char*)tp.Ag + (size_t)kt * 128;
        const char* bgb = (const char*)tp.Bg + (size_t)kt * 128;
        #pragma unroll
        for (int i = 0; i < 8; i++) {
            int lin = tid + 128 * i;
            int row = lin >> 3, c = lin & 7;
            cpasync16(sa + swz(row, c), agb + (size_t)row * tp.lda * 2 + c * 16);
        }
        #pragma unroll
        for (int i = 0; i < 8; i++) {
            int lin = tid + 128 * i;
            int row = lin >> 3, c = lin & 7;
            cpasync16(sb + swz(row, c), bgb + (size_t)row * tp.ldb * 2 + c * 16);
        }
        CP_COMMIT();
    };

    auto lda_frag = [&](uint32_t sa, int ks, uint32_t (&af)[4][4]) {
        #pragma unroll
        for (int mt = 0; mt < 4; mt++)
            ldsm4(af[mt], sa + swz(wm * 64 + mt * 16 + (lane & 15), ks * 2 + (lane >> 4)));
    };
    auto ldb_frag = [&](uint32_t sb, int ks, uint32_t (&bf)[4][4]) {
        #pragma unroll
        for (int ng = 0; ng < 4; ng++)
            ldsm4(bf[ng], sb + swz(wn * 64 + ng * 16 + (lane & 7) + ((lane >> 4) << 3),
                                   ks * 2 + ((lane >> 3) & 1)));
    };

    float acc[4][8][4];
    uint32_t afb[2][4][4], bfb[2][4][4];

    guardf(0);                    // prologue ktiles (s<=2 < NT) are all tile 0
    issue(0);
    if (S > 1) issue(1);
    if (S > 2) issue(2);

    #pragma unroll 1
    for (int s = 0; s < S; s++) {
        const int kt = s & (NT - 1);
        if (s + 2 < S) { CP_WAIT(1); } else { CP_WAIT(0); }   // stages s, s+1 resident
        __syncthreads();

        const uint32_t sa  = smu + (s % BSTAGES) * STAGE_B;
        const uint32_t sb  = sa + 16384;
        const uint32_t sa1 = smu + ((s + 1) % BSTAGES) * STAGE_B;
        const uint32_t sb1 = sa1 + 16384;

        if (s == 0) { lda_frag(sa, 0, afb[0]); ldb_frag(sb, 0, bfb[0]); }
        if (kt == 0) {
            #pragma unroll
            for (int i = 0; i < 4; i++)
                #pragma unroll
                for (int j = 0; j < 8; j++)
                    #pragma unroll
                    for (int q = 0; q < 4; q++) acc[i][j][q] = 0.f;
        }

        #pragma unroll
        for (int ks = 0; ks < 4; ks++) {
            const int cur = ks & 1, nxt = cur ^ 1;
            if (ks < 3) {
                lda_frag(sa, ks + 1, afb[nxt]);
                ldb_frag(sb, ks + 1, bfb[nxt]);
            } else if (s + 1 < S) {   // cross-ktile/tile prefetch of next ks0
                lda_frag(sa1, 0, afb[nxt]);
                ldb_frag(sb1, 0, bfb[nxt]);
            }
            #pragma unroll
            for (int mt = 0; mt < 4; mt++)
                #pragma unroll
                for (int ng = 0; ng < 4; ng++) {
                    mma16816(acc[mt][ng * 2 + 0], afb[cur][mt], &bfb[cur][ng][0]);
                    mma16816(acc[mt][ng * 2 + 1], afb[cur][mt], &bfb[cur][ng][2]);
                }
        }

        if (kt == NT - 1) epif(s >> LOGNT, acc);

        __syncthreads();                 // all warps done reading slot s%3
        if (s + 3 < S) {
            if (((s + 3) & (NT - 1)) == 0) guardf((s + 3) >> LOGNT);
            issue(s + 3);                // reuses slot s%3 (now safe)
        }
    }
}

// ---------------------------------------------------------------------------
// Fused persistent kernel. Grid = 2 * num_SMs (full residency => spin-safe).
// Ktile-balanced contiguous schedule: phase1 tiles [start1, start1+n1),
// phase2 tiles [start2, start2+n2) with cumulative-fair split so every CTA
// gets ~equal total ktiles (64/ktile-tile in phase1, 8 in phase2).
// ---------------------------------------------------------------------------
#define NTILE1 768     // (8192/128) * (1536/128)
#define NTILE2 6144    // (8192/128) * (12288/128)
#define KTOT   98304   // NTILE1*64 + NTILE2*8

__global__ void __launch_bounds__(128, 2)
fused_k(const float* __restrict__ masks, const float* __restrict__ scaling,
        float* __restrict__ out) {
    extern __shared__ __align__(16) char sm[];
    const int tid  = threadIdx.x;
    const int lane = tid & 31;
    const int wid  = tid >> 5;
    const int wm   = wid & 1;
    const int wn   = wid >> 1;
    const int bid  = blockIdx.x;
    const int G    = gridDim.x;

    // ---- schedule (contiguous, ktile-balanced) ----
    const int b1 = NTILE1 / G, r1 = NTILE1 % G;
    const int n1     = b1 + (bid < r1 ? 1 : 0);
    const int start1 = b1 * bid + (bid < r1 ? bid : r1);
    auto C2 = [&](int b) -> int {   // cumulative-fair phase2 start for CTA b
        long long kc = ((long long)KTOT * b) / G;
        long long s1 = (long long)b1 * b + (b < r1 ? b : r1);
        long long v  = (kc - 64ll * s1) >> 3;
        if (v < 0) v = 0;
        if (v > NTILE2) v = NTILE2;
        return (int)v;
    };
    const int start2 = C2(bid);
    const int n2     = C2(bid + 1) - start2;

    // ---------------- Phase 1: gemm1 ----------------
    {
        auto tilef = [&](int i) -> TilePtrs {
            int tile = start1 + i;
            int row0 = (tile / 12) << 7, col0 = (tile % 12) << 7;
            return { g_Xh + (size_t)row0 * DIN, g_Ah + (size_t)col0 * DIN, DIN, DIN };
        };
        auto guardf = [&](int) {};
        auto epif = [&](int i, float (&acc)[4][8][4]) {
            int tile = start1 + i;
            int rb = tile / 12;
            int row0 = rb << 7, col0 = (tile % 12) << 7;
            const int nad = ((col0 + wn * 64) >> 6) & 7;
            const int b   = row0 >> 11;
            const float coef = scaling[nad] * masks[nad * 4 + b];
            #pragma unroll
            for (int mt = 0; mt < 4; mt++) {
                #pragma unroll
                for (int ni = 0; ni < 8; ni++) {
                    int r = row0 + wm * 64 + mt * 16 + (lane >> 2);
                    int c = col0 + wn * 64 + ni * 8 + 2 * (lane & 3);
                    *(__half2*)(g_Hh + (size_t)r * HCOLS + c) =
                        __floats2half2_rn(acc[mt][ni][0] * coef, acc[mt][ni][1] * coef);
                    *(__half2*)(g_Hh + (size_t)(r + 8) * HCOLS + c) =
                        __floats2half2_rn(acc[mt][ni][2] * coef, acc[mt][ni][3] * coef);
                }
            }
            __threadfence();
            __syncthreads();
            if (tid == 0) atomicAdd(&g_rowcnt[rb], 1);
        };
        if (n1 > 0)
            stream_gemm<64, 6>(n1, tilef, guardf, epif, sm);
    }

    // ---------------- Phase 2: gemm2 ----------------
    {
        auto tilef = [&](int i) -> TilePtrs {
            int tile = start2 + i;
            int row0 = (tile / 96) << 7, col0 = (tile % 96) << 7;
            int comp = col0 >> 12, cl = col0 & 4095;
            return { g_Hh + (size_t)row0 * HCOLS + comp * NR,
                     g_Bh + (size_t)comp * DOUT * NR + (size_t)cl * NR, HCOLS, NR };
        };
        auto guardf = [&](int i) {
            int rb = (start2 + i) / 96;
            int v;
            do {
                asm volatile("ld.global.acquire.gpu.b32 %0, [%1];"
                             : "=r"(v) : "l"(g_rowcnt + rb) : "memory");
            } while (v < 12);
        };
        auto epif = [&](int i, float (&acc)[4][8][4]) {
            int tile = start2 + i;
            int row0 = (tile / 96) << 7, col0 = (tile % 96) << 7;
            #pragma unroll
            for (int mt = 0; mt < 4; mt++) {
                #pragma unroll
                for (int ni = 0; ni < 8; ni++) {
                    int r = row0 + wm * 64 + mt * 16 + (lane >> 2);
                    int c = col0 + wn * 64 + ni * 8 + 2 * (lane & 3);
                    *(float2*)(out + (size_t)r * OUTCOLS + c) =
                        make_float2(acc[mt][ni][0], acc[mt][ni][1]);
                    *(float2*)(out + (size_t)(r + 8) * OUTCOLS + c) =
                        make_float2(acc[mt][ni][2], acc[mt][ni][3]);
                }
            }
        };
        if (n2 > 0)
            stream_gemm<8, 3>(n2, tilef, guardf, epif, sm);
    }
}

// ---------------------------------------------------------------------------
extern "C" void kernel_launch(void* const* d_in, const int* in_sizes, int n_in,
                              void* d_out, int out_size) {
    const float* x       = (const float*)d_in[0];
    const float* masks   = (const float*)d_in[2];
    const float* scaling = (const float*)d_in[3];
    const float* qA      = (const float*)d_in[4];
    const float* qB      = (const float*)d_in[5];
    const float* kA      = (const float*)d_in[6];
    const float* kB      = (const float*)d_in[7];
    const float* vA      = (const float*)d_in[8];
    const float* vB      = (const float*)d_in[9];
    float* out = (float*)d_out;

    static int nsm = 0;
    if (nsm == 0) {
        cudaDeviceGetAttribute(&nsm, cudaDevAttrMultiProcessorCount, 0);
        if (nsm <= 0) nsm = 148;
    }

    const int SMEM = BSTAGES * STAGE_B;   // 98304 per CTA -> 2 CTAs/SM
    cudaFuncSetAttribute(fused_k, cudaFuncAttributeMaxDynamicSharedMemorySize, SMEM);

    init_flags_k<<<1, 64>>>();
    convx_k<<<(MTOT * DIN) / (512 * 8), 512>>>(x);
    transA_k<<<dim3(DIN / 32, RANK / 32, 24), dim3(32, 8)>>>(qA, kA, vA);
    transB_k<<<dim3(NR / 32, DOUT / 32, 3), dim3(32, 8)>>>(qB, kB, vB);

    fused_k<<<2 * nsm, 128, SMEM>>>(masks, scaling, out);
}

// round 10
// speedup vs baseline: 1.0465x; 1.0465x over previous
#include <cuda_runtime.h>
#include <cuda_fp16.h>
#include <cstdint>

#define DIN     4096
#define RANK    64
#define MTOT    8192
#define NR      512
#define HCOLS   1536
#define DOUT    4096
#define OUTCOLS 12288

// fp16 staging buffers (device globals; no runtime allocation allowed)
__device__ __align__(16) __half g_Xh[(size_t)MTOT * DIN];    // 64 MB
__device__ __align__(16) __half g_Ah[(size_t)HCOLS * DIN];   // 12.5 MB  [j][k]
__device__ __align__(16) __half g_Bh[(size_t)3 * DOUT * NR]; // 12.5 MB  [comp][n][k]
__device__ __align__(16) __half g_Hh[(size_t)MTOT * HCOLS];  // 25 MB    [m][j]

// ---------------------------------------------------------------------------
// PTX helpers
// ---------------------------------------------------------------------------
__device__ __forceinline__ uint32_t s2u(const void* p) {
    uint32_t a;
    asm("{ .reg .u64 t; cvta.to.shared.u64 t, %1; cvt.u32.u64 %0, t; }" : "=r"(a) : "l"(p));
    return a;
}
__device__ __forceinline__ void cpasync16(uint32_t dst, const void* src) {
    asm volatile("cp.async.cg.shared.global [%0], [%1], 16;" :: "r"(dst), "l"(src) : "memory");
}
#define CP_COMMIT()  asm volatile("cp.async.commit_group;" ::: "memory")
#define CP_WAIT(n)   asm volatile("cp.async.wait_group %0;" :: "n"(n) : "memory")

__device__ __forceinline__ void ldsm4(uint32_t* r, uint32_t a) {
    asm volatile("ldmatrix.sync.aligned.m8n8.x4.shared.b16 {%0,%1,%2,%3}, [%4];"
                 : "=r"(r[0]), "=r"(r[1]), "=r"(r[2]), "=r"(r[3]) : "r"(a));
}
__device__ __forceinline__ void mma16816(float* c, const uint32_t* a, const uint32_t* b) {
    asm volatile(
        "mma.sync.aligned.m16n8k16.row.col.f32.f16.f16.f32 "
        "{%0,%1,%2,%3},{%4,%5,%6,%7},{%8,%9},{%0,%1,%2,%3};"
        : "+f"(c[0]), "+f"(c[1]), "+f"(c[2]), "+f"(c[3])
        : "r"(a[0]), "r"(a[1]), "r"(a[2]), "r"(a[3]), "r"(b[0]), "r"(b[1]));
}
// smem tile row = 64 halves = 128B = 8 chunks of 16B; swizzle chunk ^= row&7
__device__ __forceinline__ uint32_t swz(int row, int chunk) {
    return (uint32_t)(row * 8 + (chunk ^ (row & 7))) * 16u;
}

// ---------------------------------------------------------------------------
// Prep kernels: fp32 -> fp16 convert / transpose
// ---------------------------------------------------------------------------
__global__ void convx_k(const float* __restrict__ x) {
    size_t i = ((size_t)blockIdx.x * 512 + threadIdx.x) * 8;
    float4 a = *(const float4*)(x + i);
    float4 b = *(const float4*)(x + i + 4);
    __half2 h[4];
    h[0] = __floats2half2_rn(a.x, a.y);
    h[1] = __floats2half2_rn(a.z, a.w);
    h[2] = __floats2half2_rn(b.x, b.y);
    h[3] = __floats2half2_rn(b.z, b.w);
    *(uint4*)(g_Xh + i) = *(uint4*)h;
}

__global__ void transA_k(const float* __restrict__ qA, const float* __restrict__ kA,
                         const float* __restrict__ vA) {
    __shared__ float t[32][33];
    int z = blockIdx.z, comp = z >> 3, n = z & 7;
    const float* src = (comp == 0 ? qA : (comp == 1 ? kA : vA)) + (size_t)n * DIN * RANK;
    int i0 = blockIdx.x * 32, r0 = blockIdx.y * 32;
    int tx = threadIdx.x, ty = threadIdx.y;
    #pragma unroll
    for (int q = 0; q < 4; q++)
        t[ty + q * 8][tx] = src[(size_t)(i0 + ty + q * 8) * RANK + r0 + tx];
    __syncthreads();
    size_t jb = (size_t)(comp * 512 + n * 64 + r0);
    #pragma unroll
    for (int q = 0; q < 4; q++)
        g_Ah[(jb + ty + q * 8) * DIN + i0 + tx] = __float2half_rn(t[tx][ty + q * 8]);
}

__global__ void transB_k(const float* __restrict__ qB, const float* __restrict__ kB,
                         const float* __restrict__ vB) {
    __shared__ float t[32][33];
    int comp = blockIdx.z;
    const float* src = (comp == 0 ? qB : (comp == 1 ? kB : vB));  // [512][4096]
    int k0 = blockIdx.x * 32, n0 = blockIdx.y * 32;
    int tx = threadIdx.x, ty = threadIdx.y;
    #pragma unroll
    for (int q = 0; q < 4; q++)
        t[ty + q * 8][tx] = src[(size_t)(k0 + ty + q * 8) * DOUT + n0 + tx];
    __syncthreads();
    __half* dst = g_Bh + (size_t)comp * DOUT * NR;
    #pragma unroll
    for (int q = 0; q < 4; q++)
        dst[(size_t)(n0 + ty + q * 8) * NR + k0 + tx] = __float2half_rn(t[tx][ty + q * 8]);
}

// ---------------------------------------------------------------------------
// Streaming GEMM core: continuous cp.async pipeline across ALL of a CTA's
// tiles (no drain between tiles). Tile = 128x128, warp tile m64 x n64,
// BK=64, 3-stage, ONE barrier per ktile. 128 threads, 2 CTAs/SM.
// ---------------------------------------------------------------------------
constexpr int STAGE_B = 32 * 1024;   // 16KB A + 16KB B
constexpr int BSTAGES = 3;

struct TilePtrs { const __half* Ag; const __half* Bg; int lda; int ldb; };

template <int NT, int LOGNT, class TF, class EF>
__device__ __forceinline__ void stream_gemm(int ntiles, TF tilef, EF epif, char* sm) {
    const int tid  = threadIdx.x;
    const int lane = tid & 31;
    const int wid  = tid >> 5;
    const int wm   = wid & 1;
    const int wn   = wid >> 1;
    uint32_t smu = s2u(sm);
    const int S = ntiles << LOGNT;
    if (S <= 0) return;

    auto issue = [&](int s) {
        const int it = s >> LOGNT;
        const int kt = s & (NT - 1);
        TilePtrs tp = tilef(it);
        const int slot = s % BSTAGES;
        const uint32_t sa = smu + slot * STAGE_B;
        const uint32_t sb = sa + 16384;
        const char* agb = (const char*)tp.Ag + (size_t)kt * 128;
        const char* bgb = (const char*)tp.Bg + (size_t)kt * 128;
        #pragma unroll
        for (int i = 0; i < 8; i++) {
            int lin = tid + 128 * i;
            int row = lin >> 3, c = lin & 7;
            cpasync16(sa + swz(row, c), agb + (size_t)row * tp.lda * 2 + c * 16);
        }
        #pragma unroll
        for (int i = 0; i < 8; i++) {
            int lin = tid + 128 * i;
            int row = lin >> 3, c = lin & 7;
            cpasync16(sb + swz(row, c), bgb + (size_t)row * tp.ldb * 2 + c * 16);
        }
        CP_COMMIT();
    };

    float acc[4][8][4];
    uint32_t afb[2][4][4], bfb[2][4][4];

    issue(0);
    if (S > 1) issue(1);

    #pragma unroll 1
    for (int s = 0; s < S; s++) {
        const int kt = s & (NT - 1);
        if (s + 1 < S) { CP_WAIT(1); } else { CP_WAIT(0); }   // stage s resident
        __syncthreads();
        if (s + 2 < S) issue(s + 2);    // writes slot (s-1)%3 — safe after sync

        if (kt == 0) {
            #pragma unroll
            for (int i = 0; i < 4; i++)
                #pragma unroll
                for (int j = 0; j < 8; j++)
                    #pragma unroll
                    for (int q = 0; q < 4; q++) acc[i][j][q] = 0.f;
        }

        const uint32_t sa = smu + (s % BSTAGES) * STAGE_B;
        const uint32_t sb = sa + 16384;

        // preload ks=0 fragments
        #pragma unroll
        for (int mt = 0; mt < 4; mt++)
            ldsm4(afb[0][mt], sa + swz(wm * 64 + mt * 16 + (lane & 15), (lane >> 4)));
        #pragma unroll
        for (int ng = 0; ng < 4; ng++)
            ldsm4(bfb[0][ng], sb + swz(wn * 64 + ng * 16 + (lane & 7) + ((lane >> 4) << 3),
                                       ((lane >> 3) & 1)));

        #pragma unroll
        for (int ks = 0; ks < 4; ks++) {
            const int cur = ks & 1, nxt = cur ^ 1;
            if (ks < 3) {   // prefetch next k-subtile's fragments under the MMAs
                #pragma unroll
                for (int mt = 0; mt < 4; mt++)
                    ldsm4(afb[nxt][mt],
                          sa + swz(wm * 64 + mt * 16 + (lane & 15), (ks + 1) * 2 + (lane >> 4)));
                #pragma unroll
                for (int ng = 0; ng < 4; ng++)
                    ldsm4(bfb[nxt][ng],
                          sb + swz(wn * 64 + ng * 16 + (lane & 7) + ((lane >> 4) << 3),
                                   (ks + 1) * 2 + ((lane >> 3) & 1)));
            }
            #pragma unroll
            for (int mt = 0; mt < 4; mt++)
                #pragma unroll
                for (int ng = 0; ng < 4; ng++) {
                    mma16816(acc[mt][ng * 2 + 0], afb[cur][mt], &bfb[cur][ng][0]);
                    mma16816(acc[mt][ng * 2 + 1], afb[cur][mt], &bfb[cur][ng][2]);
                }
        }

        if (kt == NT - 1) epif(s >> LOGNT, acc);
    }
}

// ---------------------------------------------------------------------------
// GEMM1: H[8192,1536] = Xh @ Ah^T, epilogue *= coef (scalar per 64-col block)
// Persistent, striped tiles (col-fastest => concurrent CTAs share X row in L2).
// ---------------------------------------------------------------------------
__global__ void __launch_bounds__(128, 2)
tc_gemm1(const float* __restrict__ masks, const float* __restrict__ scaling) {
    extern __shared__ __align__(16) char sm[];
    const int tid = threadIdx.x, lane = tid & 31, wid = tid >> 5;
    const int wm = wid & 1, wn = wid >> 1;
    const int bid = blockIdx.x, G = gridDim.x;
    const int NTILE = (MTOT / 128) * (HCOLS / 128);   // 768
    const int nt = (bid < NTILE) ? ((NTILE - 1 - bid) / G + 1) : 0;

    auto tilef = [&](int i) -> TilePtrs {
        int tile = bid + i * G;
        int row0 = (tile / 12) << 7, col0 = (tile % 12) << 7;
        return { g_Xh + (size_t)row0 * DIN, g_Ah + (size_t)col0 * DIN, DIN, DIN };
    };
    auto epif = [&](int i, float (&acc)[4][8][4]) {
        int tile = bid + i * G;
        int row0 = (tile / 12) << 7, col0 = (tile % 12) << 7;
        const int nad = ((col0 + wn * 64) >> 6) & 7;
        const int b   = row0 >> 11;
        const float coef = scaling[nad] * masks[nad * 4 + b];
        #pragma unroll
        for (int mt = 0; mt < 4; mt++) {
            #pragma unroll
            for (int ni = 0; ni < 8; ni++) {
                int r = row0 + wm * 64 + mt * 16 + (lane >> 2);
                int c = col0 + wn * 64 + ni * 8 + 2 * (lane & 3);
                *(__half2*)(g_Hh + (size_t)r * HCOLS + c) =
                    __floats2half2_rn(acc[mt][ni][0] * coef, acc[mt][ni][1] * coef);
                *(__half2*)(g_Hh + (size_t)(r + 8) * HCOLS + c) =
                    __floats2half2_rn(acc[mt][ni][2] * coef, acc[mt][ni][3] * coef);
            }
        }
    };
    if (nt > 0)
        stream_gemm<64, 6>(nt, tilef, epif, sm);
}

// ---------------------------------------------------------------------------
// GEMM2: out[8192,12288]; per comp: out = Hh_comp @ Bh_comp^T
// Persistent, striped; continuous stream kills the per-tile (NT=8) drain.
// ---------------------------------------------------------------------------
__global__ void __launch_bounds__(128, 2)
tc_gemm2(float* __restrict__ out) {
    extern __shared__ __align__(16) char sm[];
    const int tid = threadIdx.x, lane = tid & 31, wid = tid >> 5;
    const int wm = wid & 1, wn = wid >> 1;
    const int bid = blockIdx.x, G = gridDim.x;
    const int NTILE = (MTOT / 128) * (OUTCOLS / 128);  // 6144
    const int nt = (bid < NTILE) ? ((NTILE - 1 - bid) / G + 1) : 0;

    auto tilef = [&](int i) -> TilePtrs {
        int tile = bid + i * G;
        int row0 = (tile / 96) << 7, col0 = (tile % 96) << 7;
        int comp = col0 >> 12, cl = col0 & 4095;
        return { g_Hh + (size_t)row0 * HCOLS + comp * NR,
                 g_Bh + (size_t)comp * DOUT * NR + (size_t)cl * NR, HCOLS, NR };
    };
    auto epif = [&](int i, float (&acc)[4][8][4]) {
        int tile = bid + i * G;
        int row0 = (tile / 96) << 7, col0 = (tile % 96) << 7;
        #pragma unroll
        for (int mt = 0; mt < 4; mt++) {
            #pragma unroll
            for (int ni = 0; ni < 8; ni++) {
                int r = row0 + wm * 64 + mt * 16 + (lane >> 2);
                int c = col0 + wn * 64 + ni * 8 + 2 * (lane & 3);
                *(float2*)(out + (size_t)r * OUTCOLS + c) =
                    make_float2(acc[mt][ni][0], acc[mt][ni][1]);
                *(float2*)(out + (size_t)(r + 8) * OUTCOLS + c) =
                    make_float2(acc[mt][ni][2], acc[mt][ni][3]);
            }
        }
    };
    if (nt > 0)
        stream_gemm<8, 3>(nt, tilef, epif, sm);
}

// ---------------------------------------------------------------------------
extern "C" void kernel_launch(void* const* d_in, const int* in_sizes, int n_in,
                              void* d_out, int out_size) {
    const float* x       = (const float*)d_in[0];
    const float* masks   = (const float*)d_in[2];
    const float* scaling = (const float*)d_in[3];
    const float* qA      = (const float*)d_in[4];
    const float* qB      = (const float*)d_in[5];
    const float* kA      = (const float*)d_in[6];
    const float* kB      = (const float*)d_in[7];
    const float* vA      = (const float*)d_in[8];
    const float* vB      = (const float*)d_in[9];
    float* out = (float*)d_out;

    static int nsm = 0;
    if (nsm == 0) {
        cudaDeviceGetAttribute(&nsm, cudaDevAttrMultiProcessorCount, 0);
        if (nsm <= 0) nsm = 148;
    }

    const int SMEM = BSTAGES * STAGE_B;   // 98304 per CTA -> 2 CTAs/SM
    cudaFuncSetAttribute(tc_gemm1, cudaFuncAttributeMaxDynamicSharedMemorySize, SMEM);
    cudaFuncSetAttribute(tc_gemm2, cudaFuncAttributeMaxDynamicSharedMemorySize, SMEM);

    convx_k<<<(MTOT * DIN) / (512 * 8), 512>>>(x);
    transA_k<<<dim3(DIN / 32, RANK / 32, 24), dim3(32, 8)>>>(qA, kA, vA);
    transB_k<<<dim3(NR / 32, DOUT / 32, 3), dim3(32, 8)>>>(qB, kB, vB);

    tc_gemm1<<<2 * nsm, 128, SMEM>>>(masks, scaling);
    tc_gemm2<<<2 * nsm, 128, SMEM>>>(out);
}